// round 7
// baseline (speedup 1.0000x reference)
#include <cuda_runtime.h>
#include <math.h>

#define BB 32
#define TT 1000
#define HH 1024
#define C2 2048
#define RGRID 128
#define RTHREADS 256

// ---------------- device scratch (static, no allocation) ----------------
__device__ float g_w[BB * TT * C2];      // 262 MB: projected+BN-foldable gates, reused per layer
__device__ float g_h1[BB * TT * HH];     // 131 MB: layer-1 outputs
__device__ float g_h[BB * HH];           // current hidden state
__device__ float g_colsum[C2];
__device__ float g_colsumsq[C2];
__device__ float g_scale[C2];
__device__ float g_bias[C2];
__device__ float g_rowsum[2][BB];        // ping-pong LN accumulators
__device__ float g_rowsumsq[2][BB];
__device__ unsigned g_bar_count;

// ---------------- init: zero all per-layer state ----------------
__global__ void init_kernel() {
    int tid = blockIdx.x * blockDim.x + threadIdx.x;
    if (tid == 0) g_bar_count = 0u;
    if (tid < C2) { g_colsum[tid] = 0.f; g_colsumsq[tid] = 0.f; }
    if (tid < 2 * BB) {
        (&g_rowsum[0][0])[tid] = 0.f;
        (&g_rowsumsq[0][0])[tid] = 0.f;
    }
    for (int i = tid; i < BB * HH; i += gridDim.x * blockDim.x) g_h[i] = 0.f;
}

// ---------------- projection GEMM: g_w[n][c] = sum_k A[n][k] * W[c][k] ----------------
// Tiles: BM=128, BN=128, BK=16; 256 threads; 8x8 per thread.
__global__ __launch_bounds__(256)
void proj_gemm_kernel(const float* __restrict__ Ain, const float* __restrict__ W,
                      int K, int useH1) {
    const float* __restrict__ A = useH1 ? g_h1 : Ain;
    __shared__ float As[16][128];
    __shared__ float Ws[16][128];
    const int tid = threadIdx.x;
    const int bn = blockIdx.x * 128;   // column tile (2048/128 = 16)
    const int bm = blockIdx.y * 128;   // row tile (32000/128 = 250)
    const int tx = tid & 15;           // m sub-tile
    const int ty = tid >> 4;           // n sub-tile
    const int lr = tid >> 2;           // load row 0..63
    const int lk = (tid & 3) << 2;     // load k offset 0,4,8,12

    float acc[8][8];
#pragma unroll
    for (int i = 0; i < 8; i++)
#pragma unroll
        for (int j = 0; j < 8; j++) acc[i][j] = 0.f;

    for (int k0 = 0; k0 < K; k0 += 16) {
        float4 a0 = *(const float4*)&A[(bm + lr) * K + k0 + lk];
        float4 a1 = *(const float4*)&A[(bm + 64 + lr) * K + k0 + lk];
        float4 w0 = *(const float4*)&W[(bn + lr) * K + k0 + lk];
        float4 w1 = *(const float4*)&W[(bn + 64 + lr) * K + k0 + lk];
        __syncthreads();
        As[lk + 0][lr] = a0.x; As[lk + 1][lr] = a0.y; As[lk + 2][lr] = a0.z; As[lk + 3][lr] = a0.w;
        As[lk + 0][64 + lr] = a1.x; As[lk + 1][64 + lr] = a1.y; As[lk + 2][64 + lr] = a1.z; As[lk + 3][64 + lr] = a1.w;
        Ws[lk + 0][lr] = w0.x; Ws[lk + 1][lr] = w0.y; Ws[lk + 2][lr] = w0.z; Ws[lk + 3][lr] = w0.w;
        Ws[lk + 0][64 + lr] = w1.x; Ws[lk + 1][64 + lr] = w1.y; Ws[lk + 2][64 + lr] = w1.z; Ws[lk + 3][64 + lr] = w1.w;
        __syncthreads();
#pragma unroll
        for (int kk = 0; kk < 16; kk++) {
            float4 x0 = *(const float4*)&As[kk][tx * 4];
            float4 x1 = *(const float4*)&As[kk][64 + tx * 4];
            float4 y0 = *(const float4*)&Ws[kk][ty * 4];
            float4 y1 = *(const float4*)&Ws[kk][64 + ty * 4];
            float xs[8] = {x0.x, x0.y, x0.z, x0.w, x1.x, x1.y, x1.z, x1.w};
            float ys[8] = {y0.x, y0.y, y0.z, y0.w, y1.x, y1.y, y1.z, y1.w};
#pragma unroll
            for (int i = 0; i < 8; i++)
#pragma unroll
                for (int j = 0; j < 8; j++) acc[i][j] = fmaf(xs[i], ys[j], acc[i][j]);
        }
    }

#pragma unroll
    for (int i = 0; i < 8; i++) {
        int row = bm + ((i < 4) ? (tx * 4 + i) : (64 + tx * 4 + i - 4));
        float4 v0 = make_float4(acc[i][0], acc[i][1], acc[i][2], acc[i][3]);
        float4 v1 = make_float4(acc[i][4], acc[i][5], acc[i][6], acc[i][7]);
        *(float4*)&g_w[row * C2 + bn + ty * 4] = v0;
        *(float4*)&g_w[row * C2 + bn + 64 + ty * 4] = v1;
    }
}

// ---------------- BN column stats over 32000 rows ----------------
__global__ void bn_stats_kernel() {
    int c = blockIdx.x * 256 + threadIdx.x;          // gridDim.x = 8
    int n0 = blockIdx.y * (BB * TT / 64);            // gridDim.y = 64 -> 500 rows each
    float s = 0.f, ss = 0.f;
    for (int n = 0; n < BB * TT / 64; n++) {
        float v = g_w[(n0 + n) * C2 + c];
        s += v;
        ss = fmaf(v, v, ss);
    }
    atomicAdd(&g_colsum[c], s);
    atomicAdd(&g_colsumsq[c], ss);
}

__global__ void bn_finalize_kernel(const float* __restrict__ gam, const float* __restrict__ bet) {
    int c = blockIdx.x * 256 + threadIdx.x;
    float inv_n = 1.f / (float)(BB * TT);
    float mu = g_colsum[c] * inv_n;
    float var = g_colsumsq[c] * inv_n - mu * mu;
    float s = gam[c] * rsqrtf(var + 1e-5f);
    g_scale[c] = s;
    g_bias[c] = bet[c] - mu * s;
}

// ---------------- grid barrier (monotonic counter) ----------------
__device__ __forceinline__ void grid_barrier(unsigned tgt) {
    __syncthreads();
    if (threadIdx.x == 0) {
        __threadfence();
        atomicAdd(&g_bar_count, 1u);
        while (*(volatile unsigned*)&g_bar_count < tgt) {}
        __threadfence();
    }
    __syncthreads();
}

// ---------------- persistent recurrence kernel ----------------
// 128 CTAs x 256 threads, 1 CTA/SM (SMEM-limited) -> all co-resident.
// CTA cid owns gate rows j0..j0+7 (a) and H+j0..H+j0+7 (z); keeps its 16 U rows in SMEM.
__global__ __launch_bounds__(RTHREADS, 1)
void recurrence_kernel(const float* __restrict__ U, float* __restrict__ out_ext, int toH1) {
    float* __restrict__ out = toH1 ? g_h1 : out_ext;
    extern __shared__ float smem[];
    float* Us = smem;                  // [16][1024]  64 KB
    float* hs = smem + 16 * 1024;      // [32][1024] 128 KB
    float* uhs = smem + 48 * 1024;     // [32][17]
    float* scs = uhs + 32 * 17;        // [16]
    float* bis = scs + 16;             // [16]

    const int tid = threadIdx.x;
    const int cid = blockIdx.x;
    const int j0 = cid * 8;
    const int lane = tid & 31;
    const int wid = tid >> 5;
    const int rw = (wid & 3) * 4;      // 4 local gate-rows per warp
    const int bb = (wid >> 2) * 16;    // 16 batches per warp half
    const int pb = tid >> 3;           // phase-B batch
    const int pj = tid & 7;            // phase-B j within chunk

    // one-time: load U slice + folded BN affine
    for (int i = tid; i < 16 * 256; i += RTHREADS) {
        int rl = i >> 8;
        int kk = (i & 255) << 2;
        int gr = (rl < 8) ? (j0 + rl) : (HH + j0 + rl - 8);
        *(float4*)&Us[rl * 1024 + kk] = *(const float4*)&U[gr * 1024 + kk];
    }
    if (tid < 16) {
        int c = (tid < 8) ? (j0 + tid) : (HH + j0 + (tid - 8));
        scs[tid] = g_scale[c];
        bis[tid] = g_bias[c];
    }

    unsigned epoch = 0;

    for (int t = 0; t < TT; t++) {
        const int par = t & 1;
        // prefetch this step's w early (independent of barrier/h)
        float wa = g_w[(pb * TT + t) * C2 + j0 + pj];
        float wz = g_w[(pb * TT + t) * C2 + HH + j0 + pj];

        // load full h into SMEM (L2-coherent reads)
        for (int i = tid * 4; i < BB * HH; i += RTHREADS * 4)
            *(float4*)&hs[i] = __ldcg((const float4*)&g_h[i]);
        __syncthreads();

        // GEMM: uh[b][r] = sum_k h[b][k] * Us[r][k]; lanes partition k
#pragma unroll 1
        for (int g = 0; g < 2; g++) {
            const int b0 = bb + g * 8;
            float acc[8][4];
#pragma unroll
            for (int i = 0; i < 8; i++) {
                acc[i][0] = 0.f; acc[i][1] = 0.f; acc[i][2] = 0.f; acc[i][3] = 0.f;
            }
#pragma unroll 1
            for (int ch = 0; ch < 1024; ch += 128) {
                const int ko = ch + (lane << 2);
                float4 uv0 = *(const float4*)&Us[(rw + 0) * 1024 + ko];
                float4 uv1 = *(const float4*)&Us[(rw + 1) * 1024 + ko];
                float4 uv2 = *(const float4*)&Us[(rw + 2) * 1024 + ko];
                float4 uv3 = *(const float4*)&Us[(rw + 3) * 1024 + ko];
#pragma unroll
                for (int i = 0; i < 8; i++) {
                    float4 hv = *(const float4*)&hs[(b0 + i) * 1024 + ko];
                    acc[i][0] = fmaf(hv.x, uv0.x, acc[i][0]);
                    acc[i][0] = fmaf(hv.y, uv0.y, acc[i][0]);
                    acc[i][0] = fmaf(hv.z, uv0.z, acc[i][0]);
                    acc[i][0] = fmaf(hv.w, uv0.w, acc[i][0]);
                    acc[i][1] = fmaf(hv.x, uv1.x, acc[i][1]);
                    acc[i][1] = fmaf(hv.y, uv1.y, acc[i][1]);
                    acc[i][1] = fmaf(hv.z, uv1.z, acc[i][1]);
                    acc[i][1] = fmaf(hv.w, uv1.w, acc[i][1]);
                    acc[i][2] = fmaf(hv.x, uv2.x, acc[i][2]);
                    acc[i][2] = fmaf(hv.y, uv2.y, acc[i][2]);
                    acc[i][2] = fmaf(hv.z, uv2.z, acc[i][2]);
                    acc[i][2] = fmaf(hv.w, uv2.w, acc[i][2]);
                    acc[i][3] = fmaf(hv.x, uv3.x, acc[i][3]);
                    acc[i][3] = fmaf(hv.y, uv3.y, acc[i][3]);
                    acc[i][3] = fmaf(hv.z, uv3.z, acc[i][3]);
                    acc[i][3] = fmaf(hv.w, uv3.w, acc[i][3]);
                }
            }
            // butterfly-reduce each output across lanes, scatter to SMEM
#pragma unroll
            for (int i = 0; i < 8; i++) {
#pragma unroll
                for (int j = 0; j < 4; j++) {
                    float v = acc[i][j];
                    v += __shfl_xor_sync(0xffffffffu, v, 16);
                    v += __shfl_xor_sync(0xffffffffu, v, 8);
                    v += __shfl_xor_sync(0xffffffffu, v, 4);
                    v += __shfl_xor_sync(0xffffffffu, v, 2);
                    v += __shfl_xor_sync(0xffffffffu, v, 1);
                    if (lane == (i * 4 + j)) uhs[(b0 + i) * 17 + rw + j] = v;
                }
            }
        }
        __syncthreads();

        // LN partial sums for this CTA's 16 features per batch row
        if (wid == 0) {
            float s = 0.f, ss = 0.f;
#pragma unroll
            for (int r = 0; r < 16; r++) {
                float v = uhs[lane * 17 + r];
                s += v;
                ss = fmaf(v, v, ss);
            }
            atomicAdd(&g_rowsum[par][lane], s);
            atomicAdd(&g_rowsumsq[par][lane], ss);
        }
        // one CTA zeroes the other parity's accumulators for the next step
        if (cid == 0 && wid == 1) {
            g_rowsum[1 - par][lane] = 0.f;
            g_rowsumsq[1 - par][lane] = 0.f;
        }

        grid_barrier((++epoch) * RGRID);

        // phase B: LN + gates + state update
        {
            float m = __ldcg(&g_rowsum[par][pb]) * (1.f / 2048.f);
            float ms = __ldcg(&g_rowsumsq[par][pb]) * (1.f / 2048.f);
            float inv = rsqrtf(ms - m * m + 1e-5f);
            float ga = fmaf(wa, scs[pj], bis[pj]) + (uhs[pb * 17 + pj] - m) * inv;
            float gz = fmaf(wz, scs[8 + pj], bis[8 + pj]) + (uhs[pb * 17 + 8 + pj] - m) * inv;
            float z = 1.f / (1.f + expf(-gz));
            float a = fmaxf(ga, 0.f);
            float hn = fmaf(z, hs[pb * 1024 + j0 + pj], (1.f - z) * a);
            g_h[pb * HH + j0 + pj] = hn;
            out[(pb * TT + t) * HH + j0 + pj] = hn;
        }

        grid_barrier((++epoch) * RGRID);
    }
}

// ---------------- launch ----------------
extern "C" void kernel_launch(void* const* d_in, const int* in_sizes, int n_in,
                              void* d_out, int out_size) {
    const float* x  = (const float*)d_in[0];
    const float* W1 = (const float*)d_in[1];
    const float* U1 = (const float*)d_in[2];
    const float* g1 = (const float*)d_in[3];
    const float* b1 = (const float*)d_in[4];
    const float* W2 = (const float*)d_in[5];
    const float* U2 = (const float*)d_in[6];
    const float* g2 = (const float*)d_in[7];
    const float* b2 = (const float*)d_in[8];
    float* out = (float*)d_out;

    const int RSMEM = (16 * 1024 + 32 * 1024 + 32 * 17 + 32) * 4;  // 198912 B
    cudaFuncSetAttribute(recurrence_kernel, cudaFuncAttributeMaxDynamicSharedMemorySize, RSMEM);

    // ---- layer 1 ----
    init_kernel<<<32, 1024>>>();
    proj_gemm_kernel<<<dim3(16, 250), 256>>>(x, W1, 80, 0);
    bn_stats_kernel<<<dim3(8, 64), 256>>>();
    bn_finalize_kernel<<<8, 256>>>(g1, b1);
    recurrence_kernel<<<RGRID, RTHREADS, RSMEM>>>(U1, nullptr, 1);

    // ---- layer 2 ----
    init_kernel<<<32, 1024>>>();
    proj_gemm_kernel<<<dim3(16, 250), 256>>>(nullptr, W2, 1024, 1);
    bn_stats_kernel<<<dim3(8, 64), 256>>>();
    bn_finalize_kernel<<<8, 256>>>(g2, b2);
    recurrence_kernel<<<RGRID, RTHREADS, RSMEM>>>(U2, out, 0);
}